// round 2
// baseline (speedup 1.0000x reference)
#include <cuda_runtime.h>
#include <cuda_bf16.h>
#include <cstdint>

#define EPS 1e-5f
typedef unsigned long long u64;
typedef unsigned int u32;

// ---------------- device scratch (static allocation only) ----------------
__device__ float g_a1[64], g_b1[64], g_a2[64], g_b2[64];
__device__ float g_a3[2048], g_b3[2048];
__device__ u64 g_w1pair[64 * 9];       // (s,s) packed f32x2, s = sign(conv1_w)
__device__ u64 g_w2bits[64 * 9];       // conv2 sign bits over cin
__device__ u64 g_fc1bits[2048 * 49];   // fc1 weights: word j packs channels c at index c*49+j
__device__ u64 g_fc2bits[10 * 32];     // fc2 weights packed linearly
__device__ u64 g_bits1[2048 * 14 * 14];// block1 pooled sign bits (64 ch / word)
__device__ u64 g_bits2[2048 * 7 * 7];  // block2 pooled sign bits
__device__ u64 g_bits3[2048 * 32];     // fc1 signs packed (64 outs / word)

// ---------------- packed f32x2 helpers ----------------
__device__ __forceinline__ u64 fma2(u64 a, u64 b, u64 c) {
    u64 d;
    asm("fma.rn.f32x2 %0, %1, %2, %3;" : "=l"(d) : "l"(a), "l"(b), "l"(c));
    return d;
}
__device__ __forceinline__ u64 pack2(float lo, float hi) {
    u64 d;
    asm("mov.b64 %0, {%1, %2};" : "=l"(d) : "f"(lo), "f"(hi));
    return d;
}
__device__ __forceinline__ void unpack2(u64 v, float& lo, float& hi) {
    asm("mov.b64 {%0, %1}, %2;" : "=f"(lo), "=f"(hi) : "l"(v));
}

// ---------------- single merged prep kernel (all small weights) ----------------
__global__ void prep_all(const float* g1, const float* be1, const float* m1, const float* v1,
                         const float* g2, const float* be2, const float* m2, const float* v2,
                         const float* g3, const float* be3, const float* m3, const float* v3,
                         const float* w1, const float* w2, const float* wfc2) {
    int i = blockIdx.x * blockDim.x + threadIdx.x;
    if (i < 64) {
        float a = g1[i] / sqrtf(v1[i] + EPS);
        g_a1[i] = a; g_b1[i] = be1[i] - m1[i] * a;
        float a2 = g2[i] / sqrtf(v2[i] + EPS);
        g_a2[i] = a2; g_b2[i] = be2[i] - m2[i] * a2;
    }
    if (i < 2048) {
        float a = g3[i] / sqrtf(v3[i] + EPS);
        g_a3[i] = a; g_b3[i] = be3[i] - m3[i] * a;
    }
    if (i < 576) {
        float s = (w1[i] >= 0.0f) ? 1.0f : -1.0f;
        g_w1pair[i] = pack2(s, s);
        int co = i / 9, t = i % 9;
        u64 word = 0ULL;
        for (int cin = 0; cin < 64; cin++)
            if (w2[co * 576 + cin * 9 + t] >= 0.0f) word |= 1ULL << cin;
        g_w2bits[i] = word;
    }
    if (i < 320) {
        int o = i / 32, j = i % 32;
        u64 word = 0ULL;
        const float* wo = wfc2 + o * 2048 + j * 64;
        for (int r = 0; r < 64; r++)
            if (wo[r] >= 0.0f) word |= 1ULL << r;
        g_fc2bits[i] = word;
    }
}

// ---------------- coalesced fc1 weight packing ----------------
// one block per output row o; streams 3136 floats coalesced, ballot-packs,
// then transposes bit layout (bit c at word j, flat index c*49+j) via smem.
__global__ void prep_fc1(const float* __restrict__ w, int row0) {
    __shared__ u32 sbits[98];
    __shared__ u32 sp[98];
    int o = row0 + blockIdx.x;
    int tid = threadIdx.x;
    const float* wo = w + (long long)o * 3136;
#pragma unroll
    for (int it = 0; it < 13; it++) {
        int i = it * 256 + tid;
        bool v = (i < 3136) ? (wo[i] >= 0.0f) : false;
        u32 m = __ballot_sync(0xffffffffu, v);
        if ((tid & 31) == 0 && i < 3136) sbits[i >> 5] = m;
    }
    __syncthreads();
    if (tid < 98) {
        int j = tid % 49, half = tid / 49;
        u32 part = 0;
#pragma unroll
        for (int cc = 0; cc < 32; cc++) {
            int c = half * 32 + cc;
            int fi = c * 49 + j;
            part |= ((sbits[fi >> 5] >> (fi & 31)) & 1u) << cc;
        }
        sp[tid] = part;
    }
    __syncthreads();
    if (tid < 49)
        g_fc1bits[o * 49 + tid] = (u64)sp[tid] | ((u64)sp[tid + 49] << 32);
}

// ---------------- conv1 + bn1 + sign + maxpool (fused, 2 pooled px / thread) ----------------
__global__ __launch_bounds__(256) void conv1_kernel(const float* __restrict__ x) {
    __shared__ u64 sw[576];
    __shared__ float sa[64], sb[64];
    int tid = threadIdx.x;
    for (int i = tid; i < 576; i += 256) sw[i] = g_w1pair[i];
    if (tid < 64) { sa[tid] = g_a1[tid]; sb[tid] = g_b1[tid]; }
    __syncthreads();

    int idx = blockIdx.x * 256 + tid;           // 0 .. 2048*98-1
    int b = idx / 98, q = idx % 98;
    int py = q / 7, pxp = q % 7;                 // pooled-pixel pair (2*pxp, 2*pxp+1)
    const float* xb = x + b * 784;

    float pix[4][6];
#pragma unroll
    for (int i = 0; i < 4; i++) {
        int r = 2 * py - 1 + i; r = min(max(r, 0), 27);
#pragma unroll
        for (int j = 0; j < 6; j++) {
            int c = 4 * pxp - 1 + j; c = min(max(c, 0), 27);
            pix[i][j] = xb[r * 28 + c];
        }
    }
    // pp[qq][dy][tap]: packed (dx=0, dx=1) inputs for pooled pixel qq, sub-row dy
    u64 pp[2][2][9];
#pragma unroll
    for (int qq = 0; qq < 2; qq++)
#pragma unroll
        for (int dy = 0; dy < 2; dy++)
#pragma unroll
            for (int ky = 0; ky < 3; ky++)
#pragma unroll
                for (int kx = 0; kx < 3; kx++)
                    pp[qq][dy][ky * 3 + kx] =
                        pack2(pix[dy + ky][2 * qq + kx], pix[dy + ky][2 * qq + kx + 1]);

    u64 word0 = 0ULL, word1 = 0ULL;
    for (int co = 0; co < 64; co++) {
        u64 a00 = 0ULL, a01 = 0ULL, a10 = 0ULL, a11 = 0ULL;
#pragma unroll
        for (int t = 0; t < 9; t++) {
            u64 w = sw[co * 9 + t];
            a00 = fma2(w, pp[0][0][t], a00);
            a01 = fma2(w, pp[0][1][t], a01);
            a10 = fma2(w, pp[1][0][t], a10);
            a11 = fma2(w, pp[1][1][t], a11);
        }
        float v0, v1, v2, v3;
        unpack2(a00, v0, v1); unpack2(a01, v2, v3);
        float m0 = fmaxf(fmaxf(v0, v1), fmaxf(v2, v3));
        unpack2(a10, v0, v1); unpack2(a11, v2, v3);
        float m1 = fmaxf(fmaxf(v0, v1), fmaxf(v2, v3));
        float aa = sa[co], bb = sb[co];
        if (fmaf(aa, m0, bb) >= 0.0f) word0 |= 1ULL << co;
        if (fmaf(aa, m1, bb) >= 0.0f) word1 |= 1ULL << co;
    }
    u64* ob = g_bits1 + b * 196 + py * 14 + 2 * pxp;
    ob[0] = word0;
    ob[1] = word1;
}

// ---------------- conv2 + bn2 + sign + maxpool (XNOR, 2 batches / thread) ----------------
__global__ __launch_bounds__(128) void conv2_kernel() {
    __shared__ u64 sw[576];
    __shared__ float sa[64], sb[64];
    int tid = threadIdx.x;
    for (int i = tid; i < 576; i += 128) sw[i] = g_w2bits[i];
    if (tid < 64) { sa[tid] = g_a2[tid]; sb[tid] = g_b2[tid]; }
    __syncthreads();

    int idx = blockIdx.x * 128 + tid;            // 0 .. 1024*49-1
    int bp = idx / 49, p = idx % 49;
    int b0 = bp * 2;
    int py = p / 7, px = p % 7;
    const u64* i0 = g_bits1 + b0 * 196;
    const u64* i1 = i0 + 196;

    u64 pixA[16], pixB[16];
#pragma unroll
    for (int i = 0; i < 4; i++) {
        int r = 2 * py - 1 + i; r = min(max(r, 0), 13);
#pragma unroll
        for (int j = 0; j < 4; j++) {
            int c = 2 * px - 1 + j; c = min(max(c, 0), 13);
            pixA[i * 4 + j] = i0[r * 14 + c];
            pixB[i * 4 + j] = i1[r * 14 + c];
        }
    }

    u64 wordA = 0ULL, wordB = 0ULL;
    for (int co = 0; co < 64; co++) {
        u64 wreg[9];
#pragma unroll
        for (int t = 0; t < 9; t++) wreg[t] = sw[co * 9 + t];
        int sminA = 1 << 30, sminB = 1 << 30;
#pragma unroll
        for (int dy = 0; dy < 2; dy++)
#pragma unroll
            for (int dx = 0; dx < 2; dx++) {
                int sA = 0, sB = 0;
#pragma unroll
                for (int ky = 0; ky < 3; ky++)
#pragma unroll
                    for (int kx = 0; kx < 3; kx++) {
                        u64 w = wreg[ky * 3 + kx];
                        sA += __popcll(pixA[(dy + ky) * 4 + (dx + kx)] ^ w);
                        sB += __popcll(pixB[(dy + ky) * 4 + (dx + kx)] ^ w);
                    }
                sminA = min(sminA, sA);
                sminB = min(sminB, sB);
            }
        float aa = sa[co], bb = sb[co];
        if (fmaf(aa, (float)(576 - 2 * sminA), bb) >= 0.0f) wordA |= 1ULL << co;
        if (fmaf(aa, (float)(576 - 2 * sminB), bb) >= 0.0f) wordB |= 1ULL << co;
    }
    g_bits2[b0 * 49 + p] = wordA;
    g_bits2[(b0 + 1) * 49 + p] = wordB;
}

// ---------------- fc1: 2048x2048 XNOR GEMM + bn3 + sign + bit-pack ----------------
template <int KN>
__device__ __forceinline__ void fc1_accum(const u64 (&sA)[64][25], const u64 (&sB)[64][25],
                                          int tx, int ty, int (&acc)[4][4]) {
#pragma unroll 5
    for (int kk = 0; kk < KN; kk++) {
        u64 a0 = sA[ty][kk],      a1 = sA[ty + 16][kk],
            a2 = sA[ty + 32][kk], a3 = sA[ty + 48][kk];
        u64 b0 = sB[tx][kk],      b1 = sB[tx + 16][kk],
            b2 = sB[tx + 32][kk], b3 = sB[tx + 48][kk];
        acc[0][0] += __popcll(a0 ^ b0); acc[0][1] += __popcll(a0 ^ b1);
        acc[0][2] += __popcll(a0 ^ b2); acc[0][3] += __popcll(a0 ^ b3);
        acc[1][0] += __popcll(a1 ^ b0); acc[1][1] += __popcll(a1 ^ b1);
        acc[1][2] += __popcll(a1 ^ b2); acc[1][3] += __popcll(a1 ^ b3);
        acc[2][0] += __popcll(a2 ^ b0); acc[2][1] += __popcll(a2 ^ b1);
        acc[2][2] += __popcll(a2 ^ b2); acc[2][3] += __popcll(a2 ^ b3);
        acc[3][0] += __popcll(a3 ^ b0); acc[3][1] += __popcll(a3 ^ b1);
        acc[3][2] += __popcll(a3 ^ b2); acc[3][3] += __popcll(a3 ^ b3);
    }
}

__global__ __launch_bounds__(256) void fc1_kernel() {
    __shared__ u64 sA[64][25];
    __shared__ u64 sB[64][25];
    __shared__ u64 obits[64];
    __shared__ float sa3[64], sb3[64];
    int tid = threadIdx.x;
    int tx = tid & 15, ty = tid >> 4;
    int b0 = blockIdx.y * 64;
    int n0 = blockIdx.x * 64;

    if (tid < 64) {
        obits[tid] = 0ULL;
        sa3[tid] = g_a3[n0 + tid];
        sb3[tid] = g_b3[n0 + tid];
    }

    int acc[4][4];
#pragma unroll
    for (int i = 0; i < 4; i++)
#pragma unroll
        for (int j = 0; j < 4; j++) acc[i][j] = 0;

    // phase 0: k words [0,25)
    for (int e = tid; e < 64 * 25; e += 256) {
        int r = e / 25, kk = e % 25;
        sA[r][kk] = g_bits2[(b0 + r) * 49 + kk];
        sB[r][kk] = g_fc1bits[(n0 + r) * 49 + kk];
    }
    __syncthreads();
    fc1_accum<25>(sA, sB, tx, ty, acc);
    __syncthreads();
    // phase 1: k words [25,49)
    for (int e = tid; e < 64 * 24; e += 256) {
        int r = e / 24, kk = e % 24;
        sA[r][kk] = g_bits2[(b0 + r) * 49 + 25 + kk];
        sB[r][kk] = g_fc1bits[(n0 + r) * 49 + 25 + kk];
    }
    __syncthreads();
    fc1_accum<24>(sA, sB, tx, ty, acc);

    // bn3 + sign + pack bits into 64-bit words (one per tile row)
#pragma unroll
    for (int i = 0; i < 4; i++) {
        u64 bits = 0ULL;
#pragma unroll
        for (int j = 0; j < 4; j++) {
            int c = tx + 16 * j;
            float d = (float)(3136 - 2 * acc[i][j]);
            if (fmaf(sa3[c], d, sb3[c]) >= 0.0f) bits |= 1ULL << c;
        }
        atomicOr(&obits[ty + 16 * i], bits);
    }
    __syncthreads();
    if (tid < 64)
        g_bits3[(b0 + tid) * 32 + blockIdx.x] = obits[tid];
}

// ---------------- fc2: [2048,2048] x [10,2048] XNOR GEMM + scale ----------------
__global__ void fc2_kernel(float* __restrict__ out, const float* __restrict__ scale) {
    int idx = blockIdx.x * blockDim.x + threadIdx.x;
    if (idx >= 2048 * 10) return;
    int b = idx / 10, o = idx % 10;
    const u64* xb = g_bits3 + b * 32;
    const u64* wb = g_fc2bits + o * 32;
    int s = 0;
#pragma unroll
    for (int j = 0; j < 32; j++) s += __popcll(xb[j] ^ wb[j]);
    out[idx] = scale[0] * (float)(2048 - 2 * s);
}

// ---------------- launch ----------------
extern "C" void kernel_launch(void* const* d_in, const int* in_sizes, int n_in,
                              void* d_out, int out_size) {
    const float* x       = (const float*)d_in[0];
    const float* conv1_w = (const float*)d_in[1];
    const float* bn1_g   = (const float*)d_in[2];
    const float* bn1_b   = (const float*)d_in[3];
    const float* bn1_m   = (const float*)d_in[4];
    const float* bn1_v   = (const float*)d_in[5];
    const float* conv2_w = (const float*)d_in[6];
    const float* bn2_g   = (const float*)d_in[7];
    const float* bn2_b   = (const float*)d_in[8];
    const float* bn2_m   = (const float*)d_in[9];
    const float* bn2_v   = (const float*)d_in[10];
    const float* fc1_w   = (const float*)d_in[11];
    const float* bn3_g   = (const float*)d_in[12];
    const float* bn3_b   = (const float*)d_in[13];
    const float* bn3_m   = (const float*)d_in[14];
    const float* bn3_v   = (const float*)d_in[15];
    const float* fc2_w   = (const float*)d_in[16];
    const float* scale   = (const float*)d_in[17];
    float* out = (float*)d_out;

    // launch order chosen so capture slot #6 (-s 5 -c 1) = fc1_kernel
    prep_all<<<8, 256>>>(bn1_g, bn1_b, bn1_m, bn1_v,
                         bn2_g, bn2_b, bn2_m, bn2_v,
                         bn3_g, bn3_b, bn3_m, bn3_v,
                         conv1_w, conv2_w, fc2_w);
    prep_fc1<<<1024, 256>>>(fc1_w, 0);
    prep_fc1<<<1024, 256>>>(fc1_w, 1024);
    conv1_kernel<<<784, 256>>>(x);          // 2048*98 threads
    conv2_kernel<<<392, 128>>>();           // 1024*49 threads
    fc1_kernel<<<dim3(32, 32), 256>>>();
    fc2_kernel<<<80, 256>>>(out, scale);
}

// round 3
// speedup vs baseline: 1.1085x; 1.1085x over previous
#include <cuda_runtime.h>
#include <cuda_bf16.h>
#include <cstdint>

#define EPS 1e-5f
typedef unsigned long long u64;
typedef unsigned int u32;

// ---------------- device scratch (static allocation only) ----------------
__device__ float g_a1[64], g_b1[64], g_a2[64], g_b2[64];
__device__ float g_a3[2048], g_b3[2048];
__device__ u64 g_w1pair[64 * 9];       // (s,s) packed f32x2, s = sign(conv1_w)
__device__ u64 g_w2bits[64 * 9];       // conv2 sign bits over cin
__device__ u64 g_fc1bits[2048 * 49];   // fc1 weights: word j packs channels c at index c*49+j
__device__ u64 g_fc2bits[10 * 32];     // fc2 weights packed linearly
__device__ u64 g_bits1[2048 * 14 * 14];// block1 pooled sign bits (64 ch / word)
__device__ u64 g_bits2[2048 * 7 * 7];  // block2 pooled sign bits
__device__ u64 g_bits3[2048 * 32];     // fc1 signs packed (64 outs / word)

// ---------------- packed f32x2 helpers ----------------
__device__ __forceinline__ u64 fma2(u64 a, u64 b, u64 c) {
    u64 d;
    asm("fma.rn.f32x2 %0, %1, %2, %3;" : "=l"(d) : "l"(a), "l"(b), "l"(c));
    return d;
}
__device__ __forceinline__ u64 pack2(float lo, float hi) {
    u64 d;
    asm("mov.b64 %0, {%1, %2};" : "=l"(d) : "f"(lo), "f"(hi));
    return d;
}
__device__ __forceinline__ void unpack2(u64 v, float& lo, float& hi) {
    asm("mov.b64 {%0, %1}, %2;" : "=f"(lo), "=f"(hi) : "l"(v));
}

// ---------------- small prep: bn folds + conv1 weight signs ----------------
__global__ void prep_small(const float* g1, const float* be1, const float* m1, const float* v1,
                           const float* g2, const float* be2, const float* m2, const float* v2,
                           const float* g3, const float* be3, const float* m3, const float* v3,
                           const float* w1) {
    int i = blockIdx.x * blockDim.x + threadIdx.x;
    if (i < 64) {
        float a = g1[i] / sqrtf(v1[i] + EPS);
        g_a1[i] = a; g_b1[i] = be1[i] - m1[i] * a;
        float a2 = g2[i] / sqrtf(v2[i] + EPS);
        g_a2[i] = a2; g_b2[i] = be2[i] - m2[i] * a2;
    }
    if (i < 2048) {
        float a = g3[i] / sqrtf(v3[i] + EPS);
        g_a3[i] = a; g_b3[i] = be3[i] - m3[i] * a;
    }
    if (i < 576) {
        float s = (w1[i] >= 0.0f) ? 1.0f : -1.0f;
        g_w1pair[i] = pack2(s, s);
    }
}

// ---------------- conv2 weights: coalesced ballot pack, one block per co ----------------
__global__ void prep_w2(const float* __restrict__ w) {
    __shared__ u32 sbits[18];                 // 576 sign bits for this co
    int co = blockIdx.x;
    int tid = threadIdx.x;                     // 128 threads
    const float* wc = w + co * 576;
#pragma unroll
    for (int it = 0; it < 5; it++) {
        int i = it * 128 + tid;
        bool v = (i < 576) ? (wc[i] >= 0.0f) : false;
        u32 m = __ballot_sync(0xffffffffu, v);
        if ((tid & 31) == 0 && i < 576) sbits[i >> 5] = m;
    }
    __syncthreads();
    if (tid < 9) {
        u64 word = 0ULL;
#pragma unroll
        for (int cin = 0; cin < 64; cin++) {
            int fi = cin * 9 + tid;            // layout [cin, tap]
            word |= (u64)((sbits[fi >> 5] >> (fi & 31)) & 1u) << cin;
        }
        g_w2bits[co * 9 + tid] = word;
    }
}

// ---------------- fc2 weights: coalesced ballot pack, one block per output ----------------
__global__ void prep_fc2(const float* __restrict__ w) {
    __shared__ u32 sbits[64];
    int o = blockIdx.x;
    int tid = threadIdx.x;                     // 256 threads
    const float* wo = w + o * 2048;
#pragma unroll
    for (int it = 0; it < 8; it++) {
        int i = it * 256 + tid;
        u32 m = __ballot_sync(0xffffffffu, wo[i] >= 0.0f);
        if ((tid & 31) == 0) sbits[i >> 5] = m;
    }
    __syncthreads();
    if (tid < 32)
        g_fc2bits[o * 32 + tid] = (u64)sbits[2 * tid] | ((u64)sbits[2 * tid + 1] << 32);
}

// ---------------- coalesced fc1 weight packing (one block per output row) ----------------
__global__ void prep_fc1(const float* __restrict__ w) {
    __shared__ u32 sbits[98];
    __shared__ u32 sp[98];
    int o = blockIdx.x;
    int tid = threadIdx.x;
    const float* wo = w + (long long)o * 3136;
#pragma unroll
    for (int it = 0; it < 13; it++) {
        int i = it * 256 + tid;
        bool v = (i < 3136) ? (wo[i] >= 0.0f) : false;
        u32 m = __ballot_sync(0xffffffffu, v);
        if ((tid & 31) == 0 && i < 3136) sbits[i >> 5] = m;
    }
    __syncthreads();
    if (tid < 98) {
        int j = tid % 49, half = tid / 49;
        u32 part = 0;
#pragma unroll
        for (int cc = 0; cc < 32; cc++) {
            int c = half * 32 + cc;
            int fi = c * 49 + j;               // layout [ch, pix]
            part |= ((sbits[fi >> 5] >> (fi & 31)) & 1u) << cc;
        }
        sp[tid] = part;
    }
    __syncthreads();
    if (tid < 49)
        g_fc1bits[o * 49 + tid] = (u64)sp[tid] | ((u64)sp[tid + 49] << 32);
}

// ---------------- conv1 + bn1 + sign + maxpool (1 pooled px/thread, co x2 unroll) ----------------
__global__ __launch_bounds__(256) void conv1_kernel(const float* __restrict__ x) {
    __shared__ u64 sw[576];
    __shared__ float sa[64], sb[64];
    int tid = threadIdx.x;
    for (int i = tid; i < 576; i += 256) sw[i] = g_w1pair[i];
    if (tid < 64) { sa[tid] = g_a1[tid]; sb[tid] = g_b1[tid]; }
    __syncthreads();

    int idx = blockIdx.x * 256 + tid;
    if (idx >= 2048 * 196) return;
    int b = idx / 196, p = idx % 196;
    int py = p / 14, px = p % 14;
    const float* xb = x + b * 784;

    float pix[16];
#pragma unroll
    for (int i = 0; i < 4; i++) {
        int r = 2 * py - 1 + i; r = min(max(r, 0), 27);
#pragma unroll
        for (int j = 0; j < 4; j++) {
            int c = 2 * px - 1 + j; c = min(max(c, 0), 27);
            pix[i * 4 + j] = xb[r * 28 + c];
        }
    }
    // packed pixel pairs: pp[dy][tap] = (value at dx=0, value at dx=1)
    u64 pp[2][9];
#pragma unroll
    for (int dy = 0; dy < 2; dy++)
#pragma unroll
        for (int ky = 0; ky < 3; ky++)
#pragma unroll
            for (int kx = 0; kx < 3; kx++)
                pp[dy][ky * 3 + kx] =
                    pack2(pix[(dy + ky) * 4 + kx], pix[(dy + ky) * 4 + kx + 1]);

    u64 word = 0ULL;
    for (int co = 0; co < 64; co += 2) {
        u64 a00 = 0ULL, a01 = 0ULL;    // channel co, sub-rows 0/1
        u64 a10 = 0ULL, a11 = 0ULL;    // channel co+1
        const u64* w0 = &sw[co * 9];
#pragma unroll
        for (int t = 0; t < 9; t++) {
            u64 wa = w0[t], wb = w0[t + 9];
            a00 = fma2(wa, pp[0][t], a00);
            a01 = fma2(wa, pp[1][t], a01);
            a10 = fma2(wb, pp[0][t], a10);
            a11 = fma2(wb, pp[1][t], a11);
        }
        float v0, v1, v2, v3;
        unpack2(a00, v0, v1); unpack2(a01, v2, v3);
        float m0 = fmaxf(fmaxf(v0, v1), fmaxf(v2, v3));
        unpack2(a10, v0, v1); unpack2(a11, v2, v3);
        float m1 = fmaxf(fmaxf(v0, v1), fmaxf(v2, v3));
        if (fmaf(sa[co], m0, sb[co]) >= 0.0f)       word |= 1ULL << co;
        if (fmaf(sa[co + 1], m1, sb[co + 1]) >= 0.0f) word |= 1ULL << (co + 1);
    }
    g_bits1[b * 196 + p] = word;
}

// ---------------- conv2 + bn2 + sign + maxpool (XNOR-popcount, 1 px/thread) ----------------
__global__ __launch_bounds__(128) void conv2_kernel() {
    __shared__ u64 sw[576];
    __shared__ float sa[64], sb[64];
    int tid = threadIdx.x;
    for (int i = tid; i < 576; i += 128) sw[i] = g_w2bits[i];
    if (tid < 64) { sa[tid] = g_a2[tid]; sb[tid] = g_b2[tid]; }
    __syncthreads();

    int idx = blockIdx.x * 128 + tid;
    if (idx >= 2048 * 49) return;
    int b = idx / 49, p = idx % 49;
    int py = p / 7, px = p % 7;
    const u64* ib = g_bits1 + b * 196;

    u64 pix[16];
#pragma unroll
    for (int i = 0; i < 4; i++) {
        int r = 2 * py - 1 + i; r = min(max(r, 0), 13);
#pragma unroll
        for (int j = 0; j < 4; j++) {
            int c = 2 * px - 1 + j; c = min(max(c, 0), 13);
            pix[i * 4 + j] = ib[r * 14 + c];
        }
    }

    u64 word = 0ULL;
    for (int co = 0; co < 64; co++) {
        u64 wreg[9];
#pragma unroll
        for (int t = 0; t < 9; t++) wreg[t] = sw[co * 9 + t];
        int smin = 1 << 30;                // dot = 576 - 2*s -> max dot = min s
#pragma unroll
        for (int dy = 0; dy < 2; dy++)
#pragma unroll
            for (int dx = 0; dx < 2; dx++) {
                int s = 0;
#pragma unroll
                for (int ky = 0; ky < 3; ky++)
#pragma unroll
                    for (int kx = 0; kx < 3; kx++)
                        s += __popcll(pix[(dy + ky) * 4 + (dx + kx)] ^ wreg[ky * 3 + kx]);
                smin = min(smin, s);
            }
        float d = (float)(576 - 2 * smin);
        if (fmaf(sa[co], d, sb[co]) >= 0.0f) word |= 1ULL << co;
    }
    g_bits2[b * 49 + p] = word;
}

// ---------------- fc1: 2048x2048 XNOR GEMM + bn3 + sign + bit-pack ----------------
template <int KN>
__device__ __forceinline__ void fc1_accum(const u64 (&sA)[64][25], const u64 (&sB)[64][25],
                                          int tx, int ty, int (&acc)[4][4]) {
#pragma unroll 5
    for (int kk = 0; kk < KN; kk++) {
        u64 a0 = sA[ty][kk],      a1 = sA[ty + 16][kk],
            a2 = sA[ty + 32][kk], a3 = sA[ty + 48][kk];
        u64 b0 = sB[tx][kk],      b1 = sB[tx + 16][kk],
            b2 = sB[tx + 32][kk], b3 = sB[tx + 48][kk];
        acc[0][0] += __popcll(a0 ^ b0); acc[0][1] += __popcll(a0 ^ b1);
        acc[0][2] += __popcll(a0 ^ b2); acc[0][3] += __popcll(a0 ^ b3);
        acc[1][0] += __popcll(a1 ^ b0); acc[1][1] += __popcll(a1 ^ b1);
        acc[1][2] += __popcll(a1 ^ b2); acc[1][3] += __popcll(a1 ^ b3);
        acc[2][0] += __popcll(a2 ^ b0); acc[2][1] += __popcll(a2 ^ b1);
        acc[2][2] += __popcll(a2 ^ b2); acc[2][3] += __popcll(a2 ^ b3);
        acc[3][0] += __popcll(a3 ^ b0); acc[3][1] += __popcll(a3 ^ b1);
        acc[3][2] += __popcll(a3 ^ b2); acc[3][3] += __popcll(a3 ^ b3);
    }
}

__global__ __launch_bounds__(256) void fc1_kernel() {
    __shared__ u64 sA[64][25];
    __shared__ u64 sB[64][25];
    __shared__ u64 obits[64];
    __shared__ float sa3[64], sb3[64];
    int tid = threadIdx.x;
    int tx = tid & 15, ty = tid >> 4;
    int b0 = blockIdx.y * 64;
    int n0 = blockIdx.x * 64;

    if (tid < 64) {
        obits[tid] = 0ULL;
        sa3[tid] = g_a3[n0 + tid];
        sb3[tid] = g_b3[n0 + tid];
    }

    int acc[4][4];
#pragma unroll
    for (int i = 0; i < 4; i++)
#pragma unroll
        for (int j = 0; j < 4; j++) acc[i][j] = 0;

    for (int e = tid; e < 64 * 25; e += 256) {
        int r = e / 25, kk = e % 25;
        sA[r][kk] = g_bits2[(b0 + r) * 49 + kk];
        sB[r][kk] = g_fc1bits[(n0 + r) * 49 + kk];
    }
    __syncthreads();
    fc1_accum<25>(sA, sB, tx, ty, acc);
    __syncthreads();
    for (int e = tid; e < 64 * 24; e += 256) {
        int r = e / 24, kk = e % 24;
        sA[r][kk] = g_bits2[(b0 + r) * 49 + 25 + kk];
        sB[r][kk] = g_fc1bits[(n0 + r) * 49 + 25 + kk];
    }
    __syncthreads();
    fc1_accum<24>(sA, sB, tx, ty, acc);

#pragma unroll
    for (int i = 0; i < 4; i++) {
        u64 bits = 0ULL;
#pragma unroll
        for (int j = 0; j < 4; j++) {
            int c = tx + 16 * j;
            float d = (float)(3136 - 2 * acc[i][j]);
            if (fmaf(sa3[c], d, sb3[c]) >= 0.0f) bits |= 1ULL << c;
        }
        atomicOr(&obits[ty + 16 * i], bits);
    }
    __syncthreads();
    if (tid < 64)
        g_bits3[(b0 + tid) * 32 + blockIdx.x] = obits[tid];
}

// ---------------- fc2: XNOR GEMM + scale ----------------
__global__ void fc2_kernel(float* __restrict__ out, const float* __restrict__ scale) {
    int idx = blockIdx.x * blockDim.x + threadIdx.x;
    if (idx >= 2048 * 10) return;
    int b = idx / 10, o = idx % 10;
    const u64* xb = g_bits3 + b * 32;
    const u64* wb = g_fc2bits + o * 32;
    int s = 0;
#pragma unroll
    for (int j = 0; j < 32; j++) s += __popcll(xb[j] ^ wb[j]);
    out[idx] = scale[0] * (float)(2048 - 2 * s);
}

// ---------------- launch ----------------
extern "C" void kernel_launch(void* const* d_in, const int* in_sizes, int n_in,
                              void* d_out, int out_size) {
    const float* x       = (const float*)d_in[0];
    const float* conv1_w = (const float*)d_in[1];
    const float* bn1_g   = (const float*)d_in[2];
    const float* bn1_b   = (const float*)d_in[3];
    const float* bn1_m   = (const float*)d_in[4];
    const float* bn1_v   = (const float*)d_in[5];
    const float* conv2_w = (const float*)d_in[6];
    const float* bn2_g   = (const float*)d_in[7];
    const float* bn2_b   = (const float*)d_in[8];
    const float* bn2_m   = (const float*)d_in[9];
    const float* bn2_v   = (const float*)d_in[10];
    const float* fc1_w   = (const float*)d_in[11];
    const float* bn3_g   = (const float*)d_in[12];
    const float* bn3_b   = (const float*)d_in[13];
    const float* bn3_m   = (const float*)d_in[14];
    const float* bn3_v   = (const float*)d_in[15];
    const float* fc2_w   = (const float*)d_in[16];
    const float* scale   = (const float*)d_in[17];
    float* out = (float*)d_out;

    prep_small<<<8, 256>>>(bn1_g, bn1_b, bn1_m, bn1_v,
                           bn2_g, bn2_b, bn2_m, bn2_v,
                           bn3_g, bn3_b, bn3_m, bn3_v, conv1_w);
    prep_w2<<<64, 128>>>(conv2_w);
    prep_fc2<<<10, 256>>>(fc2_w);
    prep_fc1<<<2048, 256>>>(fc1_w);
    conv1_kernel<<<1568, 256>>>(x);            // 2048*196 threads
    conv2_kernel<<<784, 128>>>();              // 2048*49 threads
    fc1_kernel<<<dim3(32, 32), 256>>>();
    fc2_kernel<<<80, 256>>>(out, scale);
}

// round 5
// speedup vs baseline: 1.1300x; 1.0194x over previous
#include <cuda_runtime.h>
#include <cuda_bf16.h>
#include <cstdint>

#define EPS 1e-5f
typedef unsigned long long u64;
typedef unsigned int u32;

// ---------------- device scratch ----------------
__device__ float g_a2[64], g_b2[64];
__device__ float g_a3[2048], g_b3[2048];
__device__ u64 g_w2bits[64 * 9];        // conv2 sign bits over cin
__device__ u64 g_fc1bits[2048 * 49];    // fc1 weights: word j packs channels c at k=c*49+j
__device__ u64 g_fc2bits[10 * 32];
__device__ u64 g_bits1[2048 * 14 * 14]; // block1 pooled sign bits
__device__ u64 g_bits2[2048 * 7 * 7];   // block2 pooled sign bits
__device__ u64 g_bits3[2048 * 32];      // fc1 signs packed

// ---------------- packed f32x2 helpers ----------------
__device__ __forceinline__ u64 fma2(u64 a, u64 b, u64 c) {
    u64 d;
    asm("fma.rn.f32x2 %0, %1, %2, %3;" : "=l"(d) : "l"(a), "l"(b), "l"(c));
    return d;
}
__device__ __forceinline__ u64 pack2(float lo, float hi) {
    u64 d;
    asm("mov.b64 %0, {%1, %2};" : "=l"(d) : "f"(lo), "f"(hi));
    return d;
}
__device__ __forceinline__ void unpack2(u64 v, float& lo, float& hi) {
    asm("mov.b64 {%0, %1}, %2;" : "=f"(lo), "=f"(hi) : "l"(v));
}

// ================= K1: conv1 + ALL weight prep (role by blockIdx) =================
// blocks [0,1568):        conv1 + bn1 + sign + maxpool (one pooled px / thread)
// blocks [1568,3616):     fc1 weight pack (one output row / block)
// blocks [3616,3626):     fc2 weight pack (one output / block)
// blocks [3626,3690):     conv2 weight pack (one out-channel / block)
// blocks [3690,3698):     bn2/bn3 folds
#define NB_CONV1 1568
#define NB_FC1W  2048
#define NB_FC2W  10
#define NB_W2    64
#define NB_BN    8
#define NB_K1 (NB_CONV1 + NB_FC1W + NB_FC2W + NB_W2 + NB_BN)

__global__ __launch_bounds__(256, 4) void k1_kernel(
    const float* __restrict__ x, const float* __restrict__ w1,
    const float* __restrict__ g1, const float* __restrict__ be1,
    const float* __restrict__ m1, const float* __restrict__ v1,
    const float* __restrict__ w2,
    const float* __restrict__ g2, const float* __restrict__ be2,
    const float* __restrict__ m2, const float* __restrict__ v2,
    const float* __restrict__ wfc1,
    const float* __restrict__ g3, const float* __restrict__ be3,
    const float* __restrict__ m3, const float* __restrict__ v3,
    const float* __restrict__ wfc2)
{
    __shared__ u64 sw[576];
    __shared__ float sa[64], sb[64];
    __shared__ u32 sbits[98];
    __shared__ u32 sp[98];

    int bid = blockIdx.x;
    int tid = threadIdx.x;

    if (bid < NB_CONV1) {
        // ---- conv1 role ----
        for (int i = tid; i < 576; i += 256) {
            float s = (w1[i] >= 0.0f) ? 1.0f : -1.0f;
            sw[i] = pack2(s, s);
        }
        if (tid < 64) {
            float a = g1[tid] / sqrtf(v1[tid] + EPS);
            sa[tid] = a;
            sb[tid] = be1[tid] - m1[tid] * a;
        }
        __syncthreads();

        int idx = bid * 256 + tid;              // exactly 2048*196
        int b = idx / 196, p = idx % 196;
        int py = p / 14, px = p % 14;
        const float* xb = x + b * 784;

        u64 pr[4][3];                           // 12 distinct packed pixel pairs
#pragma unroll
        for (int r = 0; r < 4; r++) {
            int rr = 2 * py - 1 + r; rr = min(max(rr, 0), 27);
            const float* xr = xb + rr * 28;
            int c0 = max(2 * px - 1, 0);
            int c3 = min(2 * px + 2, 27);
            float f0 = xr[c0];
            float f1 = xr[2 * px];
            float f2 = xr[2 * px + 1];
            float f3 = xr[c3];
            pr[r][0] = pack2(f0, f1);
            pr[r][1] = pack2(f1, f2);
            pr[r][2] = pack2(f2, f3);
        }

        u64 word = 0ULL;
        for (int co = 0; co < 64; co += 2) {
            u64 a00 = 0ULL, a01 = 0ULL, a10 = 0ULL, a11 = 0ULL;
            const u64* w0 = &sw[co * 9];
#pragma unroll
            for (int ky = 0; ky < 3; ky++)
#pragma unroll
                for (int kx = 0; kx < 3; kx++) {
                    u64 wa = w0[ky * 3 + kx], wb = w0[9 + ky * 3 + kx];
                    a00 = fma2(wa, pr[ky][kx], a00);
                    a01 = fma2(wa, pr[ky + 1][kx], a01);
                    a10 = fma2(wb, pr[ky][kx], a10);
                    a11 = fma2(wb, pr[ky + 1][kx], a11);
                }
            float v0, v1x, v2, v3;
            unpack2(a00, v0, v1x); unpack2(a01, v2, v3);
            float m0 = fmaxf(fmaxf(v0, v1x), fmaxf(v2, v3));
            unpack2(a10, v0, v1x); unpack2(a11, v2, v3);
            float m1v = fmaxf(fmaxf(v0, v1x), fmaxf(v2, v3));
            if (fmaf(sa[co], m0, sb[co]) >= 0.0f)          word |= 1ULL << co;
            if (fmaf(sa[co + 1], m1v, sb[co + 1]) >= 0.0f) word |= 1ULL << (co + 1);
        }
        g_bits1[b * 196 + p] = word;

    } else if (bid < NB_CONV1 + NB_FC1W) {
        // ---- fc1 weight pack role (one output row) ----
        int o = bid - NB_CONV1;
        const float* wo = wfc1 + (long long)o * 3136;
#pragma unroll
        for (int it = 0; it < 13; it++) {
            int i = it * 256 + tid;
            bool v = (i < 3136) ? (wo[i] >= 0.0f) : false;
            u32 m = __ballot_sync(0xffffffffu, v);
            if ((tid & 31) == 0 && i < 3136) sbits[i >> 5] = m;
        }
        __syncthreads();
        if (tid < 98) {
            int j = tid % 49, half = tid / 49;
            u32 part = 0;
#pragma unroll
            for (int cc = 0; cc < 32; cc++) {
                int c = half * 32 + cc;
                int fi = c * 49 + j;
                part |= ((sbits[fi >> 5] >> (fi & 31)) & 1u) << cc;
            }
            sp[tid] = part;
        }
        __syncthreads();
        if (tid < 49)
            g_fc1bits[o * 49 + tid] = (u64)sp[tid] | ((u64)sp[tid + 49] << 32);

    } else if (bid < NB_CONV1 + NB_FC1W + NB_FC2W) {
        // ---- fc2 weight pack role ----
        int o = bid - NB_CONV1 - NB_FC1W;
        const float* wo = wfc2 + o * 2048;
#pragma unroll
        for (int it = 0; it < 8; it++) {
            int i = it * 256 + tid;
            u32 m = __ballot_sync(0xffffffffu, wo[i] >= 0.0f);
            if ((tid & 31) == 0) sbits[i >> 5] = m;
        }
        __syncthreads();
        if (tid < 32)
            g_fc2bits[o * 32 + tid] = (u64)sbits[2 * tid] | ((u64)sbits[2 * tid + 1] << 32);

    } else if (bid < NB_CONV1 + NB_FC1W + NB_FC2W + NB_W2) {
        // ---- conv2 weight pack role (one out-channel) ----
        int co = bid - NB_CONV1 - NB_FC1W - NB_FC2W;
        const float* wc = w2 + co * 576;
#pragma unroll
        for (int it = 0; it < 3; it++) {
            int i = it * 256 + tid;
            bool v = (i < 576) ? (wc[i] >= 0.0f) : false;
            u32 m = __ballot_sync(0xffffffffu, v);
            if ((tid & 31) == 0 && i < 576) sbits[i >> 5] = m;
        }
        __syncthreads();
        if (tid < 9) {
            u64 word = 0ULL;
#pragma unroll
            for (int cin = 0; cin < 64; cin++) {
                int fi = cin * 9 + tid;
                word |= (u64)((sbits[fi >> 5] >> (fi & 31)) & 1u) << cin;
            }
            g_w2bits[co * 9 + tid] = word;
        }

    } else {
        // ---- bn fold role ----
        int i = (bid - NB_CONV1 - NB_FC1W - NB_FC2W - NB_W2) * 256 + tid;
        if (i < 2048) {
            float a = g3[i] / sqrtf(v3[i] + EPS);
            g_a3[i] = a;
            g_b3[i] = be3[i] - m3[i] * a;
        }
        if (i < 64) {
            float a = g2[i] / sqrtf(v2[i] + EPS);
            g_a2[i] = a;
            g_b2[i] = be2[i] - m2[i] * a;
        }
    }
}

// ================= conv2 + bn2 + sign + maxpool (unchanged known-good) =================
__global__ __launch_bounds__(128) void conv2_kernel() {
    __shared__ u64 sw[576];
    __shared__ float sa[64], sb[64];
    int tid = threadIdx.x;
    for (int i = tid; i < 576; i += 128) sw[i] = g_w2bits[i];
    if (tid < 64) { sa[tid] = g_a2[tid]; sb[tid] = g_b2[tid]; }
    __syncthreads();

    int idx = blockIdx.x * 128 + tid;
    if (idx >= 2048 * 49) return;
    int b = idx / 49, p = idx % 49;
    int py = p / 7, px = p % 7;
    const u64* ib = g_bits1 + b * 196;

    u64 pix[16];
#pragma unroll
    for (int i = 0; i < 4; i++) {
        int r = 2 * py - 1 + i; r = min(max(r, 0), 13);
#pragma unroll
        for (int j = 0; j < 4; j++) {
            int c = 2 * px - 1 + j; c = min(max(c, 0), 13);
            pix[i * 4 + j] = ib[r * 14 + c];
        }
    }

    u64 word = 0ULL;
    for (int co = 0; co < 64; co++) {
        u64 wreg[9];
#pragma unroll
        for (int t = 0; t < 9; t++) wreg[t] = sw[co * 9 + t];
        int smin = 1 << 30;
#pragma unroll
        for (int dy = 0; dy < 2; dy++)
#pragma unroll
            for (int dx = 0; dx < 2; dx++) {
                int s = 0;
#pragma unroll
                for (int ky = 0; ky < 3; ky++)
#pragma unroll
                    for (int kx = 0; kx < 3; kx++)
                        s += __popcll(pix[(dy + ky) * 4 + (dx + kx)] ^ wreg[ky * 3 + kx]);
                smin = min(smin, s);
            }
        float d = (float)(576 - 2 * smin);
        if (fmaf(sa[co], d, sb[co]) >= 0.0f) word |= 1ULL << co;
    }
    g_bits2[b * 49 + p] = word;
}

// ================= fc1: XNOR GEMM + bn3 + sign + pack (unchanged known-good) =================
template <int KN>
__device__ __forceinline__ void fc1_accum(const u64 (&sA)[64][25], const u64 (&sB)[64][25],
                                          int tx, int ty, int (&acc)[4][4]) {
#pragma unroll 5
    for (int kk = 0; kk < KN; kk++) {
        u64 a0 = sA[ty][kk],      a1 = sA[ty + 16][kk],
            a2 = sA[ty + 32][kk], a3 = sA[ty + 48][kk];
        u64 b0 = sB[tx][kk],      b1 = sB[tx + 16][kk],
            b2 = sB[tx + 32][kk], b3 = sB[tx + 48][kk];
        acc[0][0] += __popcll(a0 ^ b0); acc[0][1] += __popcll(a0 ^ b1);
        acc[0][2] += __popcll(a0 ^ b2); acc[0][3] += __popcll(a0 ^ b3);
        acc[1][0] += __popcll(a1 ^ b0); acc[1][1] += __popcll(a1 ^ b1);
        acc[1][2] += __popcll(a1 ^ b2); acc[1][3] += __popcll(a1 ^ b3);
        acc[2][0] += __popcll(a2 ^ b0); acc[2][1] += __popcll(a2 ^ b1);
        acc[2][2] += __popcll(a2 ^ b2); acc[2][3] += __popcll(a2 ^ b3);
        acc[3][0] += __popcll(a3 ^ b0); acc[3][1] += __popcll(a3 ^ b1);
        acc[3][2] += __popcll(a3 ^ b2); acc[3][3] += __popcll(a3 ^ b3);
    }
}

__global__ __launch_bounds__(256) void fc1_kernel() {
    __shared__ u64 sA[64][25];
    __shared__ u64 sB[64][25];
    __shared__ u64 obits[64];
    __shared__ float sa3[64], sb3[64];
    int tid = threadIdx.x;
    int tx = tid & 15, ty = tid >> 4;
    int b0 = blockIdx.y * 64;
    int n0 = blockIdx.x * 64;

    if (tid < 64) {
        obits[tid] = 0ULL;
        sa3[tid] = g_a3[n0 + tid];
        sb3[tid] = g_b3[n0 + tid];
    }

    int acc[4][4];
#pragma unroll
    for (int i = 0; i < 4; i++)
#pragma unroll
        for (int j = 0; j < 4; j++) acc[i][j] = 0;

    for (int e = tid; e < 64 * 25; e += 256) {
        int r = e / 25, kk = e % 25;
        sA[r][kk] = g_bits2[(b0 + r) * 49 + kk];
        sB[r][kk] = g_fc1bits[(n0 + r) * 49 + kk];
    }
    __syncthreads();
    fc1_accum<25>(sA, sB, tx, ty, acc);
    __syncthreads();
    for (int e = tid; e < 64 * 24; e += 256) {
        int r = e / 24, kk = e % 24;
        sA[r][kk] = g_bits2[(b0 + r) * 49 + 25 + kk];
        sB[r][kk] = g_fc1bits[(n0 + r) * 49 + 25 + kk];
    }
    __syncthreads();
    fc1_accum<24>(sA, sB, tx, ty, acc);

#pragma unroll
    for (int i = 0; i < 4; i++) {
        u64 bits = 0ULL;
#pragma unroll
        for (int j = 0; j < 4; j++) {
            int c = tx + 16 * j;
            float d = (float)(3136 - 2 * acc[i][j]);
            if (fmaf(sa3[c], d, sb3[c]) >= 0.0f) bits |= 1ULL << c;
        }
        atomicOr(&obits[ty + 16 * i], bits);
    }
    __syncthreads();
    if (tid < 64)
        g_bits3[(b0 + tid) * 32 + blockIdx.x] = obits[tid];
}

// ================= fc2 =================
__global__ void fc2_kernel(float* __restrict__ out, const float* __restrict__ scale) {
    int idx = blockIdx.x * blockDim.x + threadIdx.x;
    if (idx >= 2048 * 10) return;
    int b = idx / 10, o = idx % 10;
    const u64* xb = g_bits3 + b * 32;
    const u64* wb = g_fc2bits + o * 32;
    int s = 0;
#pragma unroll
    for (int j = 0; j < 32; j++) s += __popcll(xb[j] ^ wb[j]);
    out[idx] = scale[0] * (float)(2048 - 2 * s);
}

// ================= launch =================
extern "C" void kernel_launch(void* const* d_in, const int* in_sizes, int n_in,
                              void* d_out, int out_size) {
    const float* x       = (const float*)d_in[0];
    const float* conv1_w = (const float*)d_in[1];
    const float* bn1_g   = (const float*)d_in[2];
    const float* bn1_b   = (const float*)d_in[3];
    const float* bn1_m   = (const float*)d_in[4];
    const float* bn1_v   = (const float*)d_in[5];
    const float* conv2_w = (const float*)d_in[6];
    const float* bn2_g   = (const float*)d_in[7];
    const float* bn2_b   = (const float*)d_in[8];
    const float* bn2_m   = (const float*)d_in[9];
    const float* bn2_v   = (const float*)d_in[10];
    const float* fc1_w   = (const float*)d_in[11];
    const float* bn3_g   = (const float*)d_in[12];
    const float* bn3_b   = (const float*)d_in[13];
    const float* bn3_m   = (const float*)d_in[14];
    const float* bn3_v   = (const float*)d_in[15];
    const float* fc2_w   = (const float*)d_in[16];
    const float* scale   = (const float*)d_in[17];
    float* out = (float*)d_out;

    k1_kernel<<<NB_K1, 256>>>(x, conv1_w,
                              bn1_g, bn1_b, bn1_m, bn1_v,
                              conv2_w,
                              bn2_g, bn2_b, bn2_m, bn2_v,
                              fc1_w,
                              bn3_g, bn3_b, bn3_m, bn3_v,
                              fc2_w);
    conv2_kernel<<<784, 128>>>();
    fc1_kernel<<<dim3(32, 32), 256>>>();
    fc2_kernel<<<80, 256>>>(out, scale);
}